// round 10
// baseline (speedup 1.0000x reference)
#include <cuda_runtime.h>
#include <math.h>

// Scratch (no allocations). Zero-initialized; last block resets for replay.
// 32 double slots, 256B apart, to spread LTS atomic serialization.
static __device__ double g_slots[32 * 32];
static __device__ unsigned int g_count;

#define LOG2_1P1 0.13750352374993502f   // log2(1.1)
#define BIGC     1.099511627776e12f     // 2^40 (exact power of two)

__device__ __forceinline__ float ex2f(float x) {
    float r; asm("ex2.approx.f32 %0, %1;" : "=f"(r) : "f"(x)); return r;
}
__device__ __forceinline__ float rcpf(float x) {
    float r; asm("rcp.approx.f32 %0, %1;" : "=f"(r) : "f"(x)); return r;
}
// sat((x - ti)*2^40) == [x >= ti] (exact except measure-zero equality);
// BIGC rides in the FFMA immediate-multiplier slot (rt_SMSP = 1).
__device__ __forceinline__ float stepc(float x, float neg_tiB) {
    return __saturatef(fmaf(x, BIGC, neg_tiB));
}

// total weight (1 + w_mid), predicate-free closed form of the where-chain:
//   min(sat(t*inv_a), sat(c2 - t*inv_cb)) + min(tail, 1) + [p<0]
// tail = quadratic approx of 2^(1 - t/d) on y in [-0.25, 0]; >= 1 for y > 0
// so the min-clamp reproduces the flat region exactly.
__device__ __forceinline__ float wmid1(float p, float t,
                                       float inv_a, float inv_cb, float c2,
                                       float inv_d) {
    float u = __saturatef(t * inv_a);
    float v = __saturatef(fmaf(t, -inv_cb, c2));
    float wlow = fminf(u, v);
    float y = fmaf(t, -inv_d, 1.0f);
    float q = fmaf(y, fmaf(y, 0.2269f, 0.69275f), 1.0f);
    float e2 = fminf(q, 1.0f);
    float pneg = __saturatef(p * -BIGC);
    return wlow + e2 + pneg;
}

__device__ __forceinline__ float row_loss(float ph, float th,
                                          float pc, float tc,
                                          float pn, float tn,
                                          int ot) {
    float sp, st, dd, wcls, W, s;

    // ---- head: thr {150,500,1000,1800,2600}, a=80 b=1500 c=1750 d=2000
    sp = stepc(ph, -150.f*BIGC) + stepc(ph, -500.f*BIGC) + stepc(ph, -1000.f*BIGC)
       + stepc(ph, -1800.f*BIGC) + stepc(ph, -2600.f*BIGC);
    st = stepc(th, -150.f*BIGC) + stepc(th, -500.f*BIGC) + stepc(th, -1000.f*BIGC)
       + stepc(th, -1800.f*BIGC) + stepc(th, -2600.f*BIGC);
    dd = sp - st;
    wcls = ex2f(fabsf(dd) * LOG2_1P1);
    W = wmid1(ph, th, 1.0f/80.f, 1.0f/250.f, 7.0f, 1.0f/2000.f);
    s = fabsf(ph - th) * (wcls * W);

    // ---- chest: thr {22,35,45,55,65}*cs == x/cs vs fixed thr; a=10 b=75 c=85 d=100
    float cs = fmaf((float)ot, 0.1f, 0.8f);
    float ics = rcpf(cs);
    float pcs = pc * ics, tcs = tc * ics;
    sp = stepc(pcs, -22.f*BIGC) + stepc(pcs, -35.f*BIGC) + stepc(pcs, -45.f*BIGC)
       + stepc(pcs, -55.f*BIGC) + stepc(pcs, -65.f*BIGC);
    st = stepc(tcs, -22.f*BIGC) + stepc(tcs, -35.f*BIGC) + stepc(tcs, -45.f*BIGC)
       + stepc(tcs, -55.f*BIGC) + stepc(tcs, -65.f*BIGC);
    dd = sp - st;
    wcls = ex2f(fabsf(dd) * LOG2_1P1);
    W = wmid1(pc, tc, 1.0f/10.f, 1.0f/10.f, 8.5f, 1.0f/100.f);
    s = fmaf(fabsf(pc - tc), wcls * W, s);

    // ---- neck: thr {0.2,0.5,1.0,1.5,2.0}, a=0.15 b=1.5 c=1.7 d=1.9
    sp = stepc(pn, -0.2f*BIGC) + stepc(pn, -0.5f*BIGC) + stepc(pn, -1.0f*BIGC)
       + stepc(pn, -1.5f*BIGC) + stepc(pn, -2.0f*BIGC);
    st = stepc(tn, -0.2f*BIGC) + stepc(tn, -0.5f*BIGC) + stepc(tn, -1.0f*BIGC)
       + stepc(tn, -1.5f*BIGC) + stepc(tn, -2.0f*BIGC);
    dd = sp - st;
    wcls = ex2f(fabsf(dd) * LOG2_1P1);
    W = wmid1(pn, tn, 1.0f/0.15f, 5.0f, 8.5f, 1.0f/1.9f);
    s = fmaf(fabsf(pn - tn), wcls * W, s);

    return s;
}

struct Stage {
    float4 p0, p1, p2, t0, t1, t2;
    int4 o;
};

__device__ __forceinline__ void load_stage(Stage& S,
                                           const float4* __restrict__ pred4,
                                           const float4* __restrict__ true4,
                                           const int4* __restrict__ ot4,
                                           long long g) {
    S.p0 = pred4[3*g + 0]; S.p1 = pred4[3*g + 1]; S.p2 = pred4[3*g + 2];
    S.t0 = true4[3*g + 0]; S.t1 = true4[3*g + 1]; S.t2 = true4[3*g + 2];
    S.o  = ot4[g];
}

__device__ __forceinline__ float stage_loss(const Stage& S) {
    float s0, s1;
    s0 = row_loss(S.p0.x, S.t0.x, S.p0.y, S.t0.y, S.p0.z, S.t0.z, S.o.x);
    s1 = row_loss(S.p0.w, S.t0.w, S.p1.x, S.t1.x, S.p1.y, S.t1.y, S.o.y);
    s0 += row_loss(S.p1.z, S.t1.z, S.p1.w, S.t1.w, S.p2.x, S.t2.x, S.o.z);
    s1 += row_loss(S.p2.y, S.t2.y, S.p2.z, S.t2.z, S.p2.w, S.t2.w, S.o.w);
    return s0 + s1;
}

// Persistent grid-stride with a 2-stage software pipeline:
// next group's 7 LDG.128 are issued before computing the current group.
__global__ void __launch_bounds__(256, 4)
k_loss(const float4* __restrict__ pred4, const float4* __restrict__ true4,
       const int4* __restrict__ ot4,
       const float* __restrict__ pred, const float* __restrict__ truep,
       const int* __restrict__ ot,
       float* __restrict__ out,
       long long n_groups, long long n_tail, long long B,
       int niter, unsigned int n_blocks) {
    const long long stride = (long long)gridDim.x * blockDim.x;
    long long g = (long long)blockIdx.x * blockDim.x + threadIdx.x;

    float s = 0.0f;
    Stage S, C;
    {
        long long gl = (g < n_groups) ? g : 0;
        load_stage(S, pred4, true4, ot4, gl);
    }
    for (int it = 0; it < niter; ++it) {
        C = S;
        bool valid = (g < n_groups);
        long long gn = g + stride;
        if (it + 1 < niter) {                 // uniform branch
            long long gl = (gn < n_groups) ? gn : 0;
            load_stage(S, pred4, true4, ot4, gl);
        }
        if (valid) s += stage_loss(C);        // predicated in partial iter
        g = gn;
    }

    // tail rows (B % 4), one thread only
    if (blockIdx.x == 0 && threadIdx.x == 0 && n_tail > 0) {
        long long base = n_groups * 4;
        for (long long r = base; r < base + n_tail; r++)
            s += row_loss(pred[3*r+0], truep[3*r+0],
                          pred[3*r+1], truep[3*r+1],
                          pred[3*r+2], truep[3*r+2], ot[r]);
    }

    // warp reduce
    #pragma unroll
    for (int o = 16; o > 0; o >>= 1)
        s += __shfl_down_sync(0xFFFFFFFFu, s, o);

    __shared__ float sh[8];
    int lane = threadIdx.x & 31, wid = threadIdx.x >> 5;
    if (lane == 0) sh[wid] = s;
    __syncthreads();
    if (wid == 0) {
        s = (lane < 8) ? sh[lane] : 0.0f;
        #pragma unroll
        for (int o = 4; o > 0; o >>= 1)
            s += __shfl_down_sync(0xFFFFFFFFu, s, o);
        if (lane == 0) {
            atomicAdd(&g_slots[(blockIdx.x & 31) * 32], (double)s);
            __threadfence();
            unsigned int done = atomicAdd(&g_count, 1u);
            if (done == n_blocks - 1) {
                double total = 0.0;
                #pragma unroll
                for (int i = 0; i < 32; i++) {
                    volatile double* sp = &g_slots[i * 32];
                    total += *sp;
                }
                out[0] = (float)(total / (double)B);
                #pragma unroll
                for (int i = 0; i < 32; i++)
                    g_slots[i * 32] = 0.0;
                g_count = 0u;
            }
        }
    }
}

extern "C" void kernel_launch(void* const* d_in, const int* in_sizes, int n_in,
                              void* d_out, int out_size) {
    const float* pred = (const float*)d_in[0];
    const float* truep = (const float*)d_in[1];
    const int* ot = (const int*)d_in[2];
    float* out = (float*)d_out;

    long long B = (long long)in_sizes[2];   // rows
    long long n_groups = B >> 2;
    long long n_tail = B & 3;

    const int threads = 256;
    long long blocks = 592;                 // 148 SMs x 4 CTAs (occupancy 4)
    long long need = (n_groups + threads - 1) / threads;
    if (blocks > need) blocks = need;
    if (blocks < 1) blocks = 1;

    long long stride = blocks * threads;
    int niter = (int)((n_groups + stride - 1) / stride);
    if (niter < 1) niter = 1;

    k_loss<<<(unsigned)blocks, threads>>>(
        (const float4*)pred, (const float4*)truep, (const int4*)ot,
        pred, truep, ot, out, n_groups, n_tail, B, niter, (unsigned)blocks);
}

// round 11
// speedup vs baseline: 1.0356x; 1.0356x over previous
#include <cuda_runtime.h>
#include <math.h>
#include <stdint.h>

// Scratch (no allocations). Zero-initialized; last block resets for replay.
static __device__ double g_slots[32 * 32];
static __device__ unsigned int g_count;

#define LOG2_1P1 0.13750352374993502f   // log2(1.1)
#define BIGC     1.099511627776e12f     // 2^40 (exact power of two)

#define ROWS    512                      // rows per pipeline stage
#define THREADS 256
#define ROWS_PER_THREAD (ROWS / THREADS) // 2

__device__ __forceinline__ float ex2f(float x) {
    float r; asm("ex2.approx.f32 %0, %1;" : "=f"(r) : "f"(x)); return r;
}
__device__ __forceinline__ float rcpf(float x) {
    float r; asm("rcp.approx.f32 %0, %1;" : "=f"(r) : "f"(x)); return r;
}
// sat((x - ti)*2^40) == [x >= ti] (exact except measure-zero equality)
__device__ __forceinline__ float stepc(float x, float neg_tiB) {
    return __saturatef(fmaf(x, BIGC, neg_tiB));
}

// total weight (1 + w_mid), predicate-free closed form (R6, exact):
__device__ __forceinline__ float wmid1(float p, float t,
                                       float inv_a, float inv_cb, float c2,
                                       float inv_d, float k2) {
    float u = __saturatef(t * inv_a);
    float v = __saturatef(fmaf(t, -inv_cb, c2));
    float wlow = fminf(u, v);
    float e2 = ex2f(fmaf(t, -inv_d, 1.0f) * k2);
    float pneg = __saturatef(p * -BIGC);
    return wlow + fminf(e2, 1.0f) + pneg;
}

__device__ __forceinline__ float row_loss(float ph, float th,
                                          float pc, float tc,
                                          float pn, float tn,
                                          int ot) {
    float sp, st, dd, wcls, W, s;

    // ---- head: thr {150,500,1000,1800,2600}, a=80 b=1500 c=1750 d=2000
    sp = stepc(ph, -150.f*BIGC) + stepc(ph, -500.f*BIGC) + stepc(ph, -1000.f*BIGC)
       + stepc(ph, -1800.f*BIGC) + stepc(ph, -2600.f*BIGC);
    st = stepc(th, -150.f*BIGC) + stepc(th, -500.f*BIGC) + stepc(th, -1000.f*BIGC)
       + stepc(th, -1800.f*BIGC) + stepc(th, -2600.f*BIGC);
    dd = sp - st;
    wcls = ex2f(fabsf(dd) * LOG2_1P1);
    W = wmid1(ph, th, 1.0f/80.f, 1.0f/250.f, 7.0f, 1.0f/2000.f, 1.0f);
    s = fabsf(ph - th) * (wcls * W);

    // ---- chest: thr {22,35,45,55,65}*cs == x/cs vs fixed thr; a=10 b=75 c=85 d=100
    float cs = fmaf((float)ot, 0.1f, 0.8f);
    float ics = rcpf(cs);
    float pcs = pc * ics, tcs = tc * ics;
    sp = stepc(pcs, -22.f*BIGC) + stepc(pcs, -35.f*BIGC) + stepc(pcs, -45.f*BIGC)
       + stepc(pcs, -55.f*BIGC) + stepc(pcs, -65.f*BIGC);
    st = stepc(tcs, -22.f*BIGC) + stepc(tcs, -35.f*BIGC) + stepc(tcs, -45.f*BIGC)
       + stepc(tcs, -55.f*BIGC) + stepc(tcs, -65.f*BIGC);
    dd = sp - st;
    wcls = ex2f(fabsf(dd) * LOG2_1P1);
    W = wmid1(pc, tc, 1.0f/10.f, 1.0f/10.f, 8.5f, 1.0f/100.f, 1.0f);
    s = fmaf(fabsf(pc - tc), wcls * W, s);

    // ---- neck: thr {0.2,0.5,1.0,1.5,2.0}, a=0.15 b=1.5 c=1.7 d=1.9
    sp = stepc(pn, -0.2f*BIGC) + stepc(pn, -0.5f*BIGC) + stepc(pn, -1.0f*BIGC)
       + stepc(pn, -1.5f*BIGC) + stepc(pn, -2.0f*BIGC);
    st = stepc(tn, -0.2f*BIGC) + stepc(tn, -0.5f*BIGC) + stepc(tn, -1.0f*BIGC)
       + stepc(tn, -1.5f*BIGC) + stepc(tn, -2.0f*BIGC);
    dd = sp - st;
    wcls = ex2f(fabsf(dd) * LOG2_1P1);
    W = wmid1(pn, tn, 1.0f/0.15f, 5.0f, 8.5f, 1.0f/1.9f, 1.0f);
    s = fmaf(fabsf(pn - tn), wcls * W, s);

    return s;
}

__device__ __forceinline__ void bulk_cp(unsigned dst, const char* src,
                                        unsigned bytes, unsigned mb) {
    asm volatile(
        "cp.async.bulk.shared::cta.global.mbarrier::complete_tx::bytes "
        "[%0], [%1], %2, [%3];"
        :: "r"(dst), "l"(src), "r"(bytes), "r"(mb) : "memory");
}

__device__ __forceinline__ void mbar_expect(unsigned mb, unsigned bytes) {
    asm volatile("mbarrier.arrive.expect_tx.shared.b64 _, [%0], %1;"
                 :: "r"(mb), "r"(bytes) : "memory");
}

__device__ __forceinline__ void mbar_wait(unsigned mb, unsigned phase) {
    asm volatile(
        "{\n\t"
        ".reg .pred P;\n\t"
        "W%=:\n\t"
        "mbarrier.try_wait.parity.acquire.cta.shared::cta.b64 P, [%0], %1, 0x989680;\n\t"
        "@!P bra W%=;\n\t"
        "}"
        :: "r"(mb), "r"(phase) : "memory");
}

// Double-buffered SMEM streaming: thread 0 issues bulk copies for stage s+1
// before the CTA waits on / computes stage s. Loads are fully async (DMA),
// so HBM stays fed during compute.
__global__ void __launch_bounds__(THREADS)
k_loss(const char* __restrict__ pred_b, const char* __restrict__ true_b,
       const char* __restrict__ ot_b,
       const float* __restrict__ pred, const float* __restrict__ truep,
       const int* __restrict__ ot,
       float* __restrict__ out,
       long long NST, long long n_tail, long long B, unsigned int n_blocks) {
    __shared__ alignas(16) float sh_p[2][ROWS * 3];
    __shared__ alignas(16) float sh_t[2][ROWS * 3];
    __shared__ alignas(16) int   sh_o[2][ROWS];
    __shared__ alignas(8) unsigned long long mbar_store[2];
    __shared__ float shred[8];

    const unsigned mb[2] = {
        (unsigned)__cvta_generic_to_shared(&mbar_store[0]),
        (unsigned)__cvta_generic_to_shared(&mbar_store[1]) };

    if (threadIdx.x == 0) {
        asm volatile("mbarrier.init.shared.b64 [%0], 1;" :: "r"(mb[0]) : "memory");
        asm volatile("mbarrier.init.shared.b64 [%0], 1;" :: "r"(mb[1]) : "memory");
    }
    __syncthreads();

    const long long G = gridDim.x;
    long long s = blockIdx.x;
    const long long niter = (s < NST) ? ((NST - 1 - s) / G + 1) : 0;

    const unsigned PT_BYTES = ROWS * 12u;   // 6144
    const unsigned OT_BYTES = ROWS * 4u;    // 2048
    const unsigned ST_BYTES = 2u * PT_BYTES + OT_BYTES;  // 14336

    // prologue: issue stage s into buffer 0
    if (niter > 0 && threadIdx.x == 0) {
        mbar_expect(mb[0], ST_BYTES);
        bulk_cp((unsigned)__cvta_generic_to_shared(&sh_p[0][0]),
                pred_b + s * (long long)PT_BYTES, PT_BYTES, mb[0]);
        bulk_cp((unsigned)__cvta_generic_to_shared(&sh_t[0][0]),
                true_b + s * (long long)PT_BYTES, PT_BYTES, mb[0]);
        bulk_cp((unsigned)__cvta_generic_to_shared(&sh_o[0][0]),
                ot_b + s * (long long)OT_BYTES, OT_BYTES, mb[0]);
    }

    float acc = 0.0f;
    for (long long it = 0; it < niter; ++it) {
        long long snext = s + G;
        if (threadIdx.x == 0 && it + 1 < niter) {
            int nb = (int)((it + 1) & 1);
            mbar_expect(mb[nb], ST_BYTES);
            bulk_cp((unsigned)__cvta_generic_to_shared(&sh_p[nb][0]),
                    pred_b + snext * (long long)PT_BYTES, PT_BYTES, mb[nb]);
            bulk_cp((unsigned)__cvta_generic_to_shared(&sh_t[nb][0]),
                    true_b + snext * (long long)PT_BYTES, PT_BYTES, mb[nb]);
            bulk_cp((unsigned)__cvta_generic_to_shared(&sh_o[nb][0]),
                    ot_b + snext * (long long)OT_BYTES, OT_BYTES, mb[nb]);
        }
        int buf = (int)(it & 1);
        mbar_wait(mb[buf], (unsigned)((it >> 1) & 1));

        const float* P = &sh_p[buf][0];
        const float* T = &sh_t[buf][0];
        const int*   O = &sh_o[buf][0];
        int r0 = threadIdx.x * ROWS_PER_THREAD;
        #pragma unroll
        for (int j = 0; j < ROWS_PER_THREAD; ++j) {
            int r = r0 + j;
            acc += row_loss(P[3*r+0], T[3*r+0],
                            P[3*r+1], T[3*r+1],
                            P[3*r+2], T[3*r+2], O[r]);
        }
        __syncthreads();   // all reads done before this buffer is re-filled
        s = snext;
    }

    // tail rows (B % ROWS), one thread of block 0 via global loads
    if (blockIdx.x == 0 && threadIdx.x == 0 && n_tail > 0) {
        long long base = NST * ROWS;
        for (long long r = base; r < base + n_tail; r++)
            acc += row_loss(pred[3*r+0], truep[3*r+0],
                            pred[3*r+1], truep[3*r+1],
                            pred[3*r+2], truep[3*r+2], ot[r]);
    }

    // warp reduce
    float v = acc;
    #pragma unroll
    for (int o = 16; o > 0; o >>= 1)
        v += __shfl_down_sync(0xFFFFFFFFu, v, o);

    int lane = threadIdx.x & 31, wid = threadIdx.x >> 5;
    if (lane == 0) shred[wid] = v;
    __syncthreads();
    if (wid == 0) {
        v = (lane < 8) ? shred[lane] : 0.0f;
        #pragma unroll
        for (int o = 4; o > 0; o >>= 1)
            v += __shfl_down_sync(0xFFFFFFFFu, v, o);
        if (lane == 0) {
            atomicAdd(&g_slots[(blockIdx.x & 31) * 32], (double)v);
            __threadfence();
            unsigned int done = atomicAdd(&g_count, 1u);
            if (done == n_blocks - 1) {
                double total = 0.0;
                #pragma unroll
                for (int i = 0; i < 32; i++) {
                    volatile double* sp = &g_slots[i * 32];
                    total += *sp;
                }
                out[0] = (float)(total / (double)B);
                #pragma unroll
                for (int i = 0; i < 32; i++)
                    g_slots[i * 32] = 0.0;
                g_count = 0u;
            }
        }
    }
}

extern "C" void kernel_launch(void* const* d_in, const int* in_sizes, int n_in,
                              void* d_out, int out_size) {
    const float* pred = (const float*)d_in[0];
    const float* truep = (const float*)d_in[1];
    const int* ot = (const int*)d_in[2];
    float* out = (float*)d_out;

    long long B = (long long)in_sizes[2];   // rows
    long long NST = B / ROWS;
    long long n_tail = B % ROWS;

    long long blocks = 592;                 // 148 SMs x 4 CTAs, one wave
    if (NST > 0 && blocks > NST) blocks = NST;
    if (blocks < 1) blocks = 1;

    k_loss<<<(unsigned)blocks, THREADS>>>(
        (const char*)pred, (const char*)truep, (const char*)ot,
        pred, truep, ot, out, NST, n_tail, B, (unsigned)blocks);
}

// round 12
// speedup vs baseline: 1.2396x; 1.1970x over previous
#include <cuda_runtime.h>
#include <math.h>
#include <stdint.h>

// Scratch (no allocations). Zero-initialized; last block resets for replay.
static __device__ double g_slots[32 * 32];
static __device__ unsigned int g_count;

#define LOG2_1P1 0.13750352374993502f   // log2(1.1)
#define BIGC     1.099511627776e12f     // 2^40 (exact power of two)

#define ROWS    512                      // rows per pipeline stage
#define THREADS 128
#define RPT     4                        // rows per thread (ROWS/THREADS)
#define STAGES  3

__device__ __forceinline__ float ex2f(float x) {
    float r; asm("ex2.approx.f32 %0, %1;" : "=f"(r) : "f"(x)); return r;
}
__device__ __forceinline__ float rcpf(float x) {
    float r; asm("rcp.approx.f32 %0, %1;" : "=f"(r) : "f"(x)); return r;
}
// sat((x - ti)*2^40) == [x >= ti] (exact except measure-zero equality)
__device__ __forceinline__ float stepc(float x, float neg_tiB) {
    return __saturatef(fmaf(x, BIGC, neg_tiB));
}

// total weight (1 + w_mid), predicate-free closed form (exact, rel_err 0.0):
//   min(sat(t*inv_a), sat(c2 - t*inv_cb)) + min(2^(1 - t/d), 1) + [p<0]
__device__ __forceinline__ float wmid1(float p, float t,
                                       float inv_a, float inv_cb, float c2,
                                       float inv_d) {
    float u = __saturatef(t * inv_a);
    float v = __saturatef(fmaf(t, -inv_cb, c2));
    float wlow = fminf(u, v);
    float e2 = ex2f(fmaf(t, -inv_d, 1.0f));
    float pneg = __saturatef(p * -BIGC);
    return wlow + fminf(e2, 1.0f) + pneg;
}

__device__ __forceinline__ float row_loss(float ph, float th,
                                          float pc, float tc,
                                          float pn, float tn,
                                          int ot) {
    float sp, st, dd, wcls, W, s;

    // ---- head: thr {150,500,1000,1800,2600}, a=80 b=1500 c=1750 d=2000
    sp = stepc(ph, -150.f*BIGC) + stepc(ph, -500.f*BIGC) + stepc(ph, -1000.f*BIGC)
       + stepc(ph, -1800.f*BIGC) + stepc(ph, -2600.f*BIGC);
    st = stepc(th, -150.f*BIGC) + stepc(th, -500.f*BIGC) + stepc(th, -1000.f*BIGC)
       + stepc(th, -1800.f*BIGC) + stepc(th, -2600.f*BIGC);
    dd = sp - st;
    wcls = ex2f(fabsf(dd) * LOG2_1P1);
    W = wmid1(ph, th, 1.0f/80.f, 1.0f/250.f, 7.0f, 1.0f/2000.f);
    s = fabsf(ph - th) * (wcls * W);

    // ---- chest: thr {22,35,45,55,65}*cs == x/cs vs fixed thr; a=10 b=75 c=85 d=100
    float cs = fmaf((float)ot, 0.1f, 0.8f);
    float ics = rcpf(cs);
    float pcs = pc * ics, tcs = tc * ics;
    sp = stepc(pcs, -22.f*BIGC) + stepc(pcs, -35.f*BIGC) + stepc(pcs, -45.f*BIGC)
       + stepc(pcs, -55.f*BIGC) + stepc(pcs, -65.f*BIGC);
    st = stepc(tcs, -22.f*BIGC) + stepc(tcs, -35.f*BIGC) + stepc(tcs, -45.f*BIGC)
       + stepc(tcs, -55.f*BIGC) + stepc(tcs, -65.f*BIGC);
    dd = sp - st;
    wcls = ex2f(fabsf(dd) * LOG2_1P1);
    W = wmid1(pc, tc, 1.0f/10.f, 1.0f/10.f, 8.5f, 1.0f/100.f);
    s = fmaf(fabsf(pc - tc), wcls * W, s);

    // ---- neck: thr {0.2,0.5,1.0,1.5,2.0}, a=0.15 b=1.5 c=1.7 d=1.9
    sp = stepc(pn, -0.2f*BIGC) + stepc(pn, -0.5f*BIGC) + stepc(pn, -1.0f*BIGC)
       + stepc(pn, -1.5f*BIGC) + stepc(pn, -2.0f*BIGC);
    st = stepc(tn, -0.2f*BIGC) + stepc(tn, -0.5f*BIGC) + stepc(tn, -1.0f*BIGC)
       + stepc(tn, -1.5f*BIGC) + stepc(tn, -2.0f*BIGC);
    dd = sp - st;
    wcls = ex2f(fabsf(dd) * LOG2_1P1);
    W = wmid1(pn, tn, 1.0f/0.15f, 5.0f, 8.5f, 1.0f/1.9f);
    s = fmaf(fabsf(pn - tn), wcls * W, s);

    return s;
}

__device__ __forceinline__ void bulk_cp(unsigned dst, const char* src,
                                        unsigned bytes, unsigned mb) {
    asm volatile(
        "cp.async.bulk.shared::cta.global.mbarrier::complete_tx::bytes "
        "[%0], [%1], %2, [%3];"
        :: "r"(dst), "l"(src), "r"(bytes), "r"(mb) : "memory");
}
__device__ __forceinline__ void mbar_expect(unsigned mb, unsigned bytes) {
    asm volatile("mbarrier.arrive.expect_tx.shared.b64 _, [%0], %1;"
                 :: "r"(mb), "r"(bytes) : "memory");
}
__device__ __forceinline__ void mbar_wait(unsigned mb, unsigned phase) {
    asm volatile(
        "{\n\t"
        ".reg .pred P;\n\t"
        "W%=:\n\t"
        "mbarrier.try_wait.parity.acquire.cta.shared::cta.b64 P, [%0], %1, 0x989680;\n\t"
        "@!P bra W%=;\n\t"
        "}"
        :: "r"(mb), "r"(phase) : "memory");
}

// 3-stage bulk-copy ring; compute reads SMEM via conflict-free LDS.128.
__global__ void __launch_bounds__(THREADS)
k_loss(const char* __restrict__ pred_b, const char* __restrict__ true_b,
       const char* __restrict__ ot_b,
       const float* __restrict__ pred, const float* __restrict__ truep,
       const int* __restrict__ ot,
       float* __restrict__ out,
       long long NST, long long n_tail, long long B, unsigned int n_blocks) {
    __shared__ alignas(16) float sh_p[STAGES][ROWS * 3];
    __shared__ alignas(16) float sh_t[STAGES][ROWS * 3];
    __shared__ alignas(16) int   sh_o[STAGES][ROWS];
    __shared__ alignas(8) unsigned long long mbar_store[STAGES];
    __shared__ float shred[4];

    unsigned mb[STAGES];
    #pragma unroll
    for (int i = 0; i < STAGES; i++)
        mb[i] = (unsigned)__cvta_generic_to_shared(&mbar_store[i]);

    if (threadIdx.x == 0) {
        #pragma unroll
        for (int i = 0; i < STAGES; i++)
            asm volatile("mbarrier.init.shared.b64 [%0], 1;" :: "r"(mb[i]) : "memory");
    }
    __syncthreads();

    const long long G = gridDim.x;
    long long s0 = blockIdx.x;
    const long long niter = (s0 < NST) ? ((NST - 1 - s0) / G + 1) : 0;

    const unsigned PT_BYTES = ROWS * 12u;                 // 6144
    const unsigned OT_BYTES = ROWS * 4u;                  // 2048
    const unsigned ST_BYTES = 2u * PT_BYTES + OT_BYTES;   // 14336

    // prologue: issue fills for stages s0, s0+G, s0+2G into bufs 0..2
    if (threadIdx.x == 0) {
        #pragma unroll
        for (int k = 0; k < STAGES; k++) {
            if (k < niter) {
                long long st_ = s0 + (long long)k * G;
                mbar_expect(mb[k], ST_BYTES);
                bulk_cp((unsigned)__cvta_generic_to_shared(&sh_p[k][0]),
                        pred_b + st_ * (long long)PT_BYTES, PT_BYTES, mb[k]);
                bulk_cp((unsigned)__cvta_generic_to_shared(&sh_t[k][0]),
                        true_b + st_ * (long long)PT_BYTES, PT_BYTES, mb[k]);
                bulk_cp((unsigned)__cvta_generic_to_shared(&sh_o[k][0]),
                        ot_b + st_ * (long long)OT_BYTES, OT_BYTES, mb[k]);
            }
        }
    }

    float acc = 0.0f;
    int buf = 0, ph = 0;
    long long scur = s0;
    for (long long it = 0; it < niter; ++it) {
        mbar_wait(mb[buf], (unsigned)ph);

        // conflict-free vector reads: 3x LDS.128 pred, 3x true, 1x int4 ot
        const float4* P4 = (const float4*)&sh_p[buf][0];
        const float4* T4 = (const float4*)&sh_t[buf][0];
        const int4*   O4 = (const int4*)&sh_o[buf][0];
        int tid = threadIdx.x;
        float4 p0 = P4[3*tid+0], p1 = P4[3*tid+1], p2 = P4[3*tid+2];
        float4 t0 = T4[3*tid+0], t1 = T4[3*tid+1], t2 = T4[3*tid+2];
        int4   o  = O4[tid];

        acc += row_loss(p0.x, t0.x, p0.y, t0.y, p0.z, t0.z, o.x);
        acc += row_loss(p0.w, t0.w, p1.x, t1.x, p1.y, t1.y, o.y);
        acc += row_loss(p1.z, t1.z, p1.w, t1.w, p2.x, t2.x, o.z);
        acc += row_loss(p2.y, t2.y, p2.z, t2.z, p2.w, t2.w, o.w);

        __syncthreads();   // buffer fully consumed before refill

        long long sfill = scur + (long long)STAGES * G;
        if (threadIdx.x == 0 && it + STAGES < niter) {
            mbar_expect(mb[buf], ST_BYTES);
            bulk_cp((unsigned)__cvta_generic_to_shared(&sh_p[buf][0]),
                    pred_b + sfill * (long long)PT_BYTES, PT_BYTES, mb[buf]);
            bulk_cp((unsigned)__cvta_generic_to_shared(&sh_t[buf][0]),
                    true_b + sfill * (long long)PT_BYTES, PT_BYTES, mb[buf]);
            bulk_cp((unsigned)__cvta_generic_to_shared(&sh_o[buf][0]),
                    ot_b + sfill * (long long)OT_BYTES, OT_BYTES, mb[buf]);
        }
        scur += G;
        if (++buf == STAGES) { buf = 0; ph ^= 1; }
    }

    // tail rows (B % ROWS), one thread of block 0 via global loads
    if (blockIdx.x == 0 && threadIdx.x == 0 && n_tail > 0) {
        long long base = NST * ROWS;
        for (long long r = base; r < base + n_tail; r++)
            acc += row_loss(pred[3*r+0], truep[3*r+0],
                            pred[3*r+1], truep[3*r+1],
                            pred[3*r+2], truep[3*r+2], ot[r]);
    }

    // warp + block reduce
    float v = acc;
    #pragma unroll
    for (int o = 16; o > 0; o >>= 1)
        v += __shfl_down_sync(0xFFFFFFFFu, v, o);

    int lane = threadIdx.x & 31, wid = threadIdx.x >> 5;
    if (lane == 0) shred[wid] = v;
    __syncthreads();
    if (wid == 0) {
        v = (lane < 4) ? shred[lane] : 0.0f;
        #pragma unroll
        for (int o = 2; o > 0; o >>= 1)
            v += __shfl_down_sync(0xFFFFFFFFu, v, o);
        if (lane == 0) {
            atomicAdd(&g_slots[(blockIdx.x & 31) * 32], (double)v);
            __threadfence();
            unsigned int done = atomicAdd(&g_count, 1u);
            if (done == n_blocks - 1) {
                double total = 0.0;
                #pragma unroll
                for (int i = 0; i < 32; i++) {
                    volatile double* sp = &g_slots[i * 32];
                    total += *sp;
                }
                out[0] = (float)(total / (double)B);
                #pragma unroll
                for (int i = 0; i < 32; i++)
                    g_slots[i * 32] = 0.0;
                g_count = 0u;
            }
        }
    }
}

extern "C" void kernel_launch(void* const* d_in, const int* in_sizes, int n_in,
                              void* d_out, int out_size) {
    const float* pred = (const float*)d_in[0];
    const float* truep = (const float*)d_in[1];
    const int* ot = (const int*)d_in[2];
    float* out = (float*)d_out;

    long long B = (long long)in_sizes[2];   // rows
    long long NST = B / ROWS;
    long long n_tail = B % ROWS;

    long long blocks = 592;                 // 148 SMs x 4 CTAs, one wave
    if (NST > 0 && blocks > NST) blocks = NST;
    if (blocks < 1) blocks = 1;

    k_loss<<<(unsigned)blocks, THREADS>>>(
        (const char*)pred, (const char*)truep, (const char*)ot,
        pred, truep, ot, out, NST, n_tail, B, (unsigned)blocks);
}

// round 13
// speedup vs baseline: 1.2411x; 1.0012x over previous
#include <cuda_runtime.h>
#include <math.h>
#include <stdint.h>

// Scratch (no allocations). Zero-initialized; last block resets for replay.
static __device__ double g_slots[32 * 32];
static __device__ unsigned int g_count;

#define LOG2_1P1 0.13750352374993502f   // log2(1.1)
#define BIGC     1.099511627776e12f     // 2^40 (exact power of two)

#define ROWS    512                      // rows per pipeline stage
#define THREADS 128
#define STAGES  2

__device__ __forceinline__ float ex2f(float x) {
    float r; asm("ex2.approx.f32 %0, %1;" : "=f"(r) : "f"(x)); return r;
}
__device__ __forceinline__ float rcpf(float x) {
    float r; asm("rcp.approx.f32 %0, %1;" : "=f"(r) : "f"(x)); return r;
}
// sat((x - ti)*2^40) == [x >= ti] (exact except measure-zero equality)
__device__ __forceinline__ float stepc(float x, float neg_tiB) {
    return __saturatef(fmaf(x, BIGC, neg_tiB));
}

// total weight (1 + w_mid), predicate-free closed form (exact, rel_err 0.0):
//   min(sat(t*inv_a), sat(c2 - t*inv_cb)) + min(2^(1 - t/d), 1) + [p<0]
__device__ __forceinline__ float wmid1(float p, float t,
                                       float inv_a, float inv_cb, float c2,
                                       float inv_d) {
    float u = __saturatef(t * inv_a);
    float v = __saturatef(fmaf(t, -inv_cb, c2));
    float wlow = fminf(u, v);
    float e2 = ex2f(fmaf(t, -inv_d, 1.0f));
    float pneg = __saturatef(p * -BIGC);
    return wlow + fminf(e2, 1.0f) + pneg;
}

__device__ __forceinline__ float row_loss(float ph, float th,
                                          float pc, float tc,
                                          float pn, float tn,
                                          int ot) {
    float sp, st, dd, wcls, W, s;

    // ---- head: thr {150,500,1000,1800,2600}, a=80 b=1500 c=1750 d=2000
    sp = stepc(ph, -150.f*BIGC) + stepc(ph, -500.f*BIGC) + stepc(ph, -1000.f*BIGC)
       + stepc(ph, -1800.f*BIGC) + stepc(ph, -2600.f*BIGC);
    st = stepc(th, -150.f*BIGC) + stepc(th, -500.f*BIGC) + stepc(th, -1000.f*BIGC)
       + stepc(th, -1800.f*BIGC) + stepc(th, -2600.f*BIGC);
    dd = sp - st;
    wcls = ex2f(fabsf(dd) * LOG2_1P1);
    W = wmid1(ph, th, 1.0f/80.f, 1.0f/250.f, 7.0f, 1.0f/2000.f);
    s = fabsf(ph - th) * (wcls * W);

    // ---- chest: thr {22,35,45,55,65}*cs == x/cs vs fixed thr; a=10 b=75 c=85 d=100
    float cs = fmaf((float)ot, 0.1f, 0.8f);
    float ics = rcpf(cs);
    float pcs = pc * ics, tcs = tc * ics;
    sp = stepc(pcs, -22.f*BIGC) + stepc(pcs, -35.f*BIGC) + stepc(pcs, -45.f*BIGC)
       + stepc(pcs, -55.f*BIGC) + stepc(pcs, -65.f*BIGC);
    st = stepc(tcs, -22.f*BIGC) + stepc(tcs, -35.f*BIGC) + stepc(tcs, -45.f*BIGC)
       + stepc(tcs, -55.f*BIGC) + stepc(tcs, -65.f*BIGC);
    dd = sp - st;
    wcls = ex2f(fabsf(dd) * LOG2_1P1);
    W = wmid1(pc, tc, 1.0f/10.f, 1.0f/10.f, 8.5f, 1.0f/100.f);
    s = fmaf(fabsf(pc - tc), wcls * W, s);

    // ---- neck: thr {0.2,0.5,1.0,1.5,2.0}, a=0.15 b=1.5 c=1.7 d=1.9
    sp = stepc(pn, -0.2f*BIGC) + stepc(pn, -0.5f*BIGC) + stepc(pn, -1.0f*BIGC)
       + stepc(pn, -1.5f*BIGC) + stepc(pn, -2.0f*BIGC);
    st = stepc(tn, -0.2f*BIGC) + stepc(tn, -0.5f*BIGC) + stepc(tn, -1.0f*BIGC)
       + stepc(tn, -1.5f*BIGC) + stepc(tn, -2.0f*BIGC);
    dd = sp - st;
    wcls = ex2f(fabsf(dd) * LOG2_1P1);
    W = wmid1(pn, tn, 1.0f/0.15f, 5.0f, 8.5f, 1.0f/1.9f);
    s = fmaf(fabsf(pn - tn), wcls * W, s);

    return s;
}

__device__ __forceinline__ void bulk_cp(unsigned dst, const char* src,
                                        unsigned bytes, unsigned mb) {
    asm volatile(
        "cp.async.bulk.shared::cta.global.mbarrier::complete_tx::bytes "
        "[%0], [%1], %2, [%3];"
        :: "r"(dst), "l"(src), "r"(bytes), "r"(mb) : "memory");
}
__device__ __forceinline__ void mbar_expect(unsigned mb, unsigned bytes) {
    asm volatile("mbarrier.arrive.expect_tx.shared.b64 _, [%0], %1;"
                 :: "r"(mb), "r"(bytes) : "memory");
}
__device__ __forceinline__ void mbar_wait(unsigned mb, unsigned phase) {
    asm volatile(
        "{\n\t"
        ".reg .pred P;\n\t"
        "W%=:\n\t"
        "mbarrier.try_wait.parity.acquire.cta.shared::cta.b64 P, [%0], %1, 0x989680;\n\t"
        "@!P bra W%=;\n\t"
        "}"
        :: "r"(mb), "r"(phase) : "memory");
}

// 2-stage bulk-copy ring, 7 CTAs/SM: cross-CTA interleaving hides the
// per-CTA refill latency; compute reads SMEM via conflict-free LDS.128.
__global__ void __launch_bounds__(THREADS, 7)
k_loss(const char* __restrict__ pred_b, const char* __restrict__ true_b,
       const char* __restrict__ ot_b,
       const float* __restrict__ pred, const float* __restrict__ truep,
       const int* __restrict__ ot,
       float* __restrict__ out,
       long long NST, long long n_tail, long long B, unsigned int n_blocks) {
    __shared__ alignas(16) float sh_p[STAGES][ROWS * 3];
    __shared__ alignas(16) float sh_t[STAGES][ROWS * 3];
    __shared__ alignas(16) int   sh_o[STAGES][ROWS];
    __shared__ alignas(8) unsigned long long mbar_store[STAGES];
    __shared__ float shred[4];

    unsigned mb[STAGES];
    #pragma unroll
    for (int i = 0; i < STAGES; i++)
        mb[i] = (unsigned)__cvta_generic_to_shared(&mbar_store[i]);

    if (threadIdx.x == 0) {
        #pragma unroll
        for (int i = 0; i < STAGES; i++)
            asm volatile("mbarrier.init.shared.b64 [%0], 1;" :: "r"(mb[i]) : "memory");
    }
    __syncthreads();

    const long long G = gridDim.x;
    long long s0 = blockIdx.x;
    const long long niter = (s0 < NST) ? ((NST - 1 - s0) / G + 1) : 0;

    const unsigned PT_BYTES = ROWS * 12u;                 // 6144
    const unsigned OT_BYTES = ROWS * 4u;                  // 2048
    const unsigned ST_BYTES = 2u * PT_BYTES + OT_BYTES;   // 14336

    // prologue: issue fills for stages s0, s0+G into bufs 0..1
    if (threadIdx.x == 0) {
        #pragma unroll
        for (int k = 0; k < STAGES; k++) {
            if (k < niter) {
                long long st_ = s0 + (long long)k * G;
                mbar_expect(mb[k], ST_BYTES);
                bulk_cp((unsigned)__cvta_generic_to_shared(&sh_p[k][0]),
                        pred_b + st_ * (long long)PT_BYTES, PT_BYTES, mb[k]);
                bulk_cp((unsigned)__cvta_generic_to_shared(&sh_t[k][0]),
                        true_b + st_ * (long long)PT_BYTES, PT_BYTES, mb[k]);
                bulk_cp((unsigned)__cvta_generic_to_shared(&sh_o[k][0]),
                        ot_b + st_ * (long long)OT_BYTES, OT_BYTES, mb[k]);
            }
        }
    }

    float acc = 0.0f;
    int buf = 0, ph = 0;
    long long scur = s0;
    for (long long it = 0; it < niter; ++it) {
        mbar_wait(mb[buf], (unsigned)ph);

        // conflict-free vector reads: 3x LDS.128 pred, 3x true, 1x int4 ot
        const float4* P4 = (const float4*)&sh_p[buf][0];
        const float4* T4 = (const float4*)&sh_t[buf][0];
        const int4*   O4 = (const int4*)&sh_o[buf][0];
        int tid = threadIdx.x;
        float4 p0 = P4[3*tid+0], p1 = P4[3*tid+1], p2 = P4[3*tid+2];
        float4 t0 = T4[3*tid+0], t1 = T4[3*tid+1], t2 = T4[3*tid+2];
        int4   o  = O4[tid];

        acc += row_loss(p0.x, t0.x, p0.y, t0.y, p0.z, t0.z, o.x);
        acc += row_loss(p0.w, t0.w, p1.x, t1.x, p1.y, t1.y, o.y);
        acc += row_loss(p1.z, t1.z, p1.w, t1.w, p2.x, t2.x, o.z);
        acc += row_loss(p2.y, t2.y, p2.z, t2.z, p2.w, t2.w, o.w);

        __syncthreads();   // buffer fully consumed before refill

        long long sfill = scur + (long long)STAGES * G;
        if (threadIdx.x == 0 && it + STAGES < niter) {
            mbar_expect(mb[buf], ST_BYTES);
            bulk_cp((unsigned)__cvta_generic_to_shared(&sh_p[buf][0]),
                    pred_b + sfill * (long long)PT_BYTES, PT_BYTES, mb[buf]);
            bulk_cp((unsigned)__cvta_generic_to_shared(&sh_t[buf][0]),
                    true_b + sfill * (long long)PT_BYTES, PT_BYTES, mb[buf]);
            bulk_cp((unsigned)__cvta_generic_to_shared(&sh_o[buf][0]),
                    ot_b + sfill * (long long)OT_BYTES, OT_BYTES, mb[buf]);
        }
        scur += G;
        if (++buf == STAGES) { buf = 0; ph ^= 1; }
    }

    // tail rows (B % ROWS), one thread of block 0 via global loads
    if (blockIdx.x == 0 && threadIdx.x == 0 && n_tail > 0) {
        long long base = NST * ROWS;
        for (long long r = base; r < base + n_tail; r++)
            acc += row_loss(pred[3*r+0], truep[3*r+0],
                            pred[3*r+1], truep[3*r+1],
                            pred[3*r+2], truep[3*r+2], ot[r]);
    }

    // warp + block reduce
    float v = acc;
    #pragma unroll
    for (int o = 16; o > 0; o >>= 1)
        v += __shfl_down_sync(0xFFFFFFFFu, v, o);

    int lane = threadIdx.x & 31, wid = threadIdx.x >> 5;
    if (lane == 0) shred[wid] = v;
    __syncthreads();
    if (wid == 0) {
        v = (lane < 4) ? shred[lane] : 0.0f;
        #pragma unroll
        for (int o = 2; o > 0; o >>= 1)
            v += __shfl_down_sync(0xFFFFFFFFu, v, o);
        if (lane == 0) {
            atomicAdd(&g_slots[(blockIdx.x & 31) * 32], (double)v);
            __threadfence();
            unsigned int done = atomicAdd(&g_count, 1u);
            if (done == n_blocks - 1) {
                double total = 0.0;
                #pragma unroll
                for (int i = 0; i < 32; i++) {
                    volatile double* sp = &g_slots[i * 32];
                    total += *sp;
                }
                out[0] = (float)(total / (double)B);
                #pragma unroll
                for (int i = 0; i < 32; i++)
                    g_slots[i * 32] = 0.0;
                g_count = 0u;
            }
        }
    }
}

extern "C" void kernel_launch(void* const* d_in, const int* in_sizes, int n_in,
                              void* d_out, int out_size) {
    const float* pred = (const float*)d_in[0];
    const float* truep = (const float*)d_in[1];
    const int* ot = (const int*)d_in[2];
    float* out = (float*)d_out;

    long long B = (long long)in_sizes[2];   // rows
    long long NST = B / ROWS;
    long long n_tail = B % ROWS;

    long long blocks = 1036;                // 148 SMs x 7 CTAs, one wave
    if (NST > 0 && blocks > NST) blocks = NST;
    if (blocks < 1) blocks = 1;

    k_loss<<<(unsigned)blocks, THREADS>>>(
        (const char*)pred, (const char*)truep, (const char*)ot,
        pred, truep, ot, out, NST, n_tail, B, (unsigned)blocks);
}